// round 6
// baseline (speedup 1.0000x reference)
#include <cuda_runtime.h>
#include <cuda_bf16.h>
#include <math.h>
#include <stdint.h>

#define NTOK 8192
#define DIM  1024
#define FFN  4096
#define NE   10

typedef __nv_bfloat16 bf16;

// ---------------- scratch (device globals: no allocation allowed) ----------
__device__ bf16  g_Ab [(size_t)NTOK * FFN];   // gelu activations, bf16
__device__ float g_H  [(size_t)NTOK * DIM];   // h (fp32)
__device__ float g_Xg [(size_t)NTOK * DIM];   // gathered x, fp32 (residual/mix)
__device__ bf16  g_Xb [(size_t)NTOK * DIM];   // x bf16 (token order)
__device__ bf16  g_Xgb[(size_t)NTOK * DIM];   // gathered x bf16 (perm order)
__device__ int   g_perm[NTOK];
__device__ int   g_cnt[NE];
__device__ int   g_off[NE];
__device__ int   g_cur[NE];
__device__ int   g_tileTab[80];               // (e<<16)|rowTileIdx
__device__ int   g_ntile;

// transposed bf16 weights: Wt[n*K + k] = bf16(W[k*N + n])
__device__ bf16 g_sW1t[(size_t)FFN * DIM];
__device__ bf16 g_sW2t[(size_t)DIM * FFN];
__device__ bf16 g_sWgt[(size_t)DIM * DIM];
__device__ bf16 g_dW1t[(size_t)NE * FFN * DIM];
__device__ bf16 g_dW2t[(size_t)NE * DIM * FFN];
__device__ bf16 g_dWgt[(size_t)NE * DIM * DIM];

// ---------------- PTX helpers ------------------------------------------------
__device__ __forceinline__ uint32_t smem_u32(const void* p) {
    uint32_t a;
    asm("{ .reg .u64 t; cvta.to.shared.u64 t, %1; cvt.u32.u64 %0, t; }" : "=r"(a) : "l"(p));
    return a;
}
__device__ __forceinline__ void cp16(uint32_t dst, const void* src, int srcbytes) {
    asm volatile("cp.async.cg.shared.global [%0], [%1], 16, %2;"
                 :: "r"(dst), "l"(src), "r"(srcbytes) : "memory");
}
__device__ __forceinline__ void cp_commit() {
    asm volatile("cp.async.commit_group;" ::: "memory");
}
template <int N>
__device__ __forceinline__ void cp_wait() {
    asm volatile("cp.async.wait_group %0;" :: "n"(N) : "memory");
}
__device__ __forceinline__ void ldsm_x4(uint32_t* r, uint32_t addr) {
    asm volatile("ldmatrix.sync.aligned.m8n8.x4.shared.b16 {%0,%1,%2,%3}, [%4];"
                 : "=r"(r[0]), "=r"(r[1]), "=r"(r[2]), "=r"(r[3]) : "r"(addr));
}
__device__ __forceinline__ void ldsm_x2(uint32_t* r, uint32_t addr) {
    asm volatile("ldmatrix.sync.aligned.m8n8.x2.shared.b16 {%0,%1}, [%2];"
                 : "=r"(r[0]), "=r"(r[1]) : "r"(addr));
}
__device__ __forceinline__ void mma_bf16(float* c, const uint32_t* a, const uint32_t* b) {
    asm volatile(
        "mma.sync.aligned.m16n8k16.row.col.f32.bf16.bf16.f32 "
        "{%0,%1,%2,%3},{%4,%5,%6,%7},{%8,%9},{%0,%1,%2,%3};"
        : "+f"(c[0]), "+f"(c[1]), "+f"(c[2]), "+f"(c[3])
        : "r"(a[0]), "r"(a[1]), "r"(a[2]), "r"(a[3]), "r"(b[0]), "r"(b[1]));
}

// ---------------- routing ---------------------------------------------------
__global__ void k_zero() {
    int i = threadIdx.x;
    if (i < NE) { g_cnt[i] = 0; g_cur[i] = 0; }
}
__global__ void k_count(const int* __restrict__ ids) {
    int i = blockIdx.x * blockDim.x + threadIdx.x;
    if (i < NTOK) atomicAdd(&g_cnt[ids[i]], 1);
}
__global__ void k_scan() {
    if (threadIdx.x == 0) {
        int s = 0;
        for (int e = 0; e < NE; e++) { g_off[e] = s; s += g_cnt[e]; }
        int t = 0;
        for (int e = 0; e < NE; e++) {
            int nt = (g_cnt[e] + 127) >> 7;
            for (int q = 0; q < nt; q++) g_tileTab[t++] = (e << 16) | q;
        }
        g_ntile = t;
    }
}
__global__ void k_scatter(const int* __restrict__ ids) {
    int i = blockIdx.x * blockDim.x + threadIdx.x;
    if (i < NTOK) {
        int e = ids[i];
        int p = g_off[e] + atomicAdd(&g_cur[e], 1);
        g_perm[p] = i;
    }
}
__global__ void k_gather(const float* __restrict__ x) {
    int p   = blockIdx.x;
    int src = g_perm[p];
    float4 v = ((const float4*)(x + (size_t)src * DIM))[threadIdx.x];
    ((float4*)(g_Xg + (size_t)p * DIM))[threadIdx.x] = v;
    union { __nv_bfloat162 h; uint32_t u; } a, b;
    a.h = __floats2bfloat162_rn(v.x, v.y);
    b.h = __floats2bfloat162_rn(v.z, v.w);
    ((uint2*)(g_Xgb + (size_t)p * DIM))[threadIdx.x] = make_uint2(a.u, b.u);
}

// ---------------- converts ---------------------------------------------------
__global__ void k_cvt_x(const float* __restrict__ x) {
    int i = blockIdx.x * blockDim.x + threadIdx.x;
    float4 v = ((const float4*)x)[i];
    union { __nv_bfloat162 h; uint32_t u; } a, b;
    a.h = __floats2bfloat162_rn(v.x, v.y);
    b.h = __floats2bfloat162_rn(v.z, v.w);
    ((uint2*)g_Xb)[i] = make_uint2(a.u, b.u);
}
__global__ void k_transpose(const float* __restrict__ W, int K, int N, int which) {
    bf16* Wt = which == 0 ? g_sW1t : which == 1 ? g_sW2t : which == 2 ? g_sWgt
             : which == 3 ? g_dW1t : which == 4 ? g_dW2t : g_dWgt;
    int e = blockIdx.z;
    W  += (size_t)e * K * N;
    Wt += (size_t)e * K * N;
    __shared__ float t[32][33];
    int n0 = blockIdx.x * 32, k0 = blockIdx.y * 32;
#pragma unroll
    for (int i = threadIdx.y; i < 32; i += 8)
        t[i][threadIdx.x] = W[(size_t)(k0 + i) * N + n0 + threadIdx.x];
    __syncthreads();
#pragma unroll
    for (int i = threadIdx.y; i < 32; i += 8)
        Wt[(size_t)(n0 + i) * K + k0 + threadIdx.x] = __float2bfloat16(t[threadIdx.x][i]);
}

// ---------------- bf16 tensor-core GEMM --------------------------------------
// BM=128, BN=128, BK=32, 256 threads (8 warps 2x4), warp tile 64x32.
// 3-stage cp.async pipeline, one __syncthreads per K-chunk.
#define APAD   40                 // row stride in elems (80B), conflict-free ldmatrix
#define BUFB   (128 * APAD)       // elems per operand per stage
#define STAGES 3
#define SMEM_BYTES (STAGES * 2 * BUFB * 2)

template <int MODE, bool DOMAIN>
__global__ void __launch_bounds__(256, 2) gemm_k(
    const float* __restrict__ xf,
    const float* __restrict__ biasBase,
    float*       __restrict__ Fout,
    int K, int Nd)
{
    int e = 0, Mloc = NTOK, rowBase = 0, rowTile;
    if (DOMAIN) {
        int idx = blockIdx.y;
        if (idx >= g_ntile) return;
        int pk  = g_tileTab[idx];
        e       = pk >> 16;
        rowTile = (pk & 0xffff) * 128;
        Mloc    = g_cnt[e];
        rowBase = g_off[e];
    } else {
        rowTile = blockIdx.y * 128;
    }

    const bf16* A;
    if (MODE == 1) A = g_Ab + (size_t)rowBase * K;
    else           A = (DOMAIN ? g_Xgb : g_Xb) + (size_t)rowBase * K;
    const bf16* Wt =
        MODE == 0 ? (DOMAIN ? g_dW1t : g_sW1t)
      : MODE == 1 ? (DOMAIN ? g_dW2t : g_sW2t)
                  : (DOMAIN ? g_dWgt : g_sWgt);
    if (DOMAIN) Wt += (size_t)e * K * Nd;
    const float* bias = biasBase + (DOMAIN ? (size_t)e * Nd : 0);
    const float* Xr   = DOMAIN ? g_Xg : xf;

    extern __shared__ bf16 sm[];
    uint32_t asb = smem_u32(sm);                          // A stages
    uint32_t bsb = asb + STAGES * BUFB * 2;               // B stages

    int tid   = threadIdx.x;
    int lane  = tid & 31;
    int warp  = tid >> 5;
    int warpM = warp >> 2;
    int warpN = warp & 3;

    int colTile = blockIdx.x * 128;

    int srow = tid >> 2;          // 0..63
    int sseg = (tid & 3) * 8;     // elem offset within 32-elem chunk row

    int aoff = (lane & 15) * APAD + ((lane >> 4) << 3);
    int boff = (lane & 7)  * APAD + (((lane >> 3) & 1) << 3);

    float acc[4][4][4];
#pragma unroll
    for (int mi = 0; mi < 4; mi++)
#pragma unroll
        for (int ni = 0; ni < 4; ni++)
#pragma unroll
            for (int j = 0; j < 4; j++) acc[mi][ni][j] = 0.f;

    const int chunks = K >> 5;

    // issue one chunk into a stage slot
    auto issue = [&](int chunk, int slot) {
        int kk = chunk * 32;
        uint32_t aOff = asb + (uint32_t)slot * BUFB * 2;
        uint32_t bOff = bsb + (uint32_t)slot * BUFB * 2;
#pragma unroll
        for (int i = 0; i < 2; i++) {
            int row = srow + i * 64;
            int av  = (rowTile + row) < Mloc ? 16 : 0;
            cp16(aOff + (uint32_t)(row * APAD + sseg) * 2,
                 A + (size_t)(rowTile + row) * K + kk + sseg, av);
            cp16(bOff + (uint32_t)(row * APAD + sseg) * 2,
                 Wt + (size_t)(colTile + row) * K + kk + sseg, 16);
        }
        cp_commit();
    };

    issue(0, 0);
    issue(1, 1);

    int sCur = 0;
    for (int i = 0; i < chunks; i++) {
        if (i + 1 < chunks) cp_wait<1>();   // chunk i done; i+1 may be in flight
        else                cp_wait<0>();   // final chunk: drain fully
        __syncthreads();

        if (i + 2 < chunks) {
            int slot = sCur + 2; if (slot >= STAGES) slot -= STAGES;
            issue(i + 2, slot);             // safe: that slot's compute ended iter i-1
        }

        uint32_t aBuf = asb + (uint32_t)sCur * BUFB * 2;
        uint32_t bBuf = bsb + (uint32_t)sCur * BUFB * 2;
#pragma unroll
        for (int kb = 0; kb < 32; kb += 16) {
            uint32_t af[4][4], bfr[4][2];
#pragma unroll
            for (int mi = 0; mi < 4; mi++)
                ldsm_x4(af[mi], aBuf + (uint32_t)((warpM * 64 + mi * 16) * APAD + kb + aoff) * 2);
#pragma unroll
            for (int ni = 0; ni < 4; ni++)
                ldsm_x2(bfr[ni], bBuf + (uint32_t)((warpN * 32 + ni * 8) * APAD + kb + boff) * 2);
#pragma unroll
            for (int mi = 0; mi < 4; mi++)
#pragma unroll
                for (int ni = 0; ni < 4; ni++)
                    mma_bf16(acc[mi][ni], af[mi], bfr[ni]);
        }
        if (++sCur == STAGES) sCur = 0;
    }

    // ---------------- epilogue ----------------
    int grp = lane >> 2;
    int t4  = lane & 3;
#pragma unroll
    for (int mi = 0; mi < 4; mi++) {
#pragma unroll
        for (int h = 0; h < 2; h++) {
            int lr = rowTile + warpM * 64 + mi * 16 + grp + h * 8;
            if (lr >= Mloc) continue;
            int grow = rowBase + lr;
#pragma unroll
            for (int ni = 0; ni < 4; ni++) {
                int col = colTile + warpN * 32 + ni * 8 + t4 * 2;
                float v0 = acc[mi][ni][h * 2 + 0];
                float v1 = acc[mi][ni][h * 2 + 1];

                if (MODE == 0) {
                    float a0 = v0 + bias[col];
                    float a1 = v1 + bias[col + 1];
                    a0 = 0.5f * a0 * (1.0f + erff(a0 * 0.70710678118654752f));
                    a1 = 0.5f * a1 * (1.0f + erff(a1 * 0.70710678118654752f));
                    union { __nv_bfloat162 h2; uint32_t u; } cv;
                    cv.h2 = __floats2bfloat162_rn(a0, a1);
                    *(uint32_t*)(g_Ab + (size_t)grow * Nd + col) = cv.u;
                } else if (MODE == 1) {
                    float*       dst = g_H + (size_t)grow * Nd + col;
                    const float* r   = Xr  + (size_t)grow * Nd + col;
                    dst[0] = v0 + bias[col]     + r[0];
                    dst[1] = v1 + bias[col + 1] + r[1];
                } else {
                    const float* hp = g_H + (size_t)grow * Nd + col;
                    const float* xp = Xr  + (size_t)grow * Nd + col;
                    int orow = DOMAIN ? g_perm[grow] : grow;
                    float* dst = Fout + (size_t)orow * Nd + col;
                    float g0 = 1.0f / (1.0f + expf(-(v0 + bias[col])));
                    float g1 = 1.0f / (1.0f + expf(-(v1 + bias[col + 1])));
                    float o0 = g0 * hp[0] + (1.0f - g0) * xp[0];
                    float o1 = g1 * hp[1] + (1.0f - g1) * xp[1];
                    if (DOMAIN) { dst[0] += o0; dst[1] += o1; }
                    else        { dst[0]  = o0; dst[1]  = o1; }
                }
            }
        }
    }
}

// ---------------- launch -----------------------------------------------------
extern "C" void kernel_launch(void* const* d_in, const int* in_sizes, int n_in,
                              void* d_out, int out_size)
{
    const float* x   = (const float*)d_in[0];
    const int*   ids = (const int*)  d_in[1];
    const float* sW1 = (const float*)d_in[2];
    const float* sb1 = (const float*)d_in[3];
    const float* sW2 = (const float*)d_in[4];
    const float* sb2 = (const float*)d_in[5];
    const float* sWg = (const float*)d_in[6];
    const float* sbg = (const float*)d_in[7];
    const float* dW1 = (const float*)d_in[8];
    const float* db1 = (const float*)d_in[9];
    const float* dW2 = (const float*)d_in[10];
    const float* db2 = (const float*)d_in[11];
    const float* dWg = (const float*)d_in[12];
    const float* dbg = (const float*)d_in[13];
    float* out = (float*)d_out;

    // raise dynamic smem cap for all gemm instantiations (idempotent, capture-safe)
    cudaFuncSetAttribute(gemm_k<0, false>, cudaFuncAttributeMaxDynamicSharedMemorySize, SMEM_BYTES);
    cudaFuncSetAttribute(gemm_k<1, false>, cudaFuncAttributeMaxDynamicSharedMemorySize, SMEM_BYTES);
    cudaFuncSetAttribute(gemm_k<2, false>, cudaFuncAttributeMaxDynamicSharedMemorySize, SMEM_BYTES);
    cudaFuncSetAttribute(gemm_k<0, true>,  cudaFuncAttributeMaxDynamicSharedMemorySize, SMEM_BYTES);
    cudaFuncSetAttribute(gemm_k<1, true>,  cudaFuncAttributeMaxDynamicSharedMemorySize, SMEM_BYTES);
    cudaFuncSetAttribute(gemm_k<2, true>,  cudaFuncAttributeMaxDynamicSharedMemorySize, SMEM_BYTES);

    // routing + converts
    k_zero   <<<1, 32>>>();
    k_count  <<<NTOK / 256, 256>>>(ids);
    k_scan   <<<1, 32>>>();
    k_scatter<<<NTOK / 256, 256>>>(ids);
    k_gather <<<NTOK, 256>>>(x);
    k_cvt_x  <<<NTOK * DIM / 4 / 256, 256>>>(x);

    dim3 tb(32, 8);
    k_transpose<<<dim3(FFN / 32, DIM / 32, 1),  tb>>>(sW1, DIM, FFN, 0);
    k_transpose<<<dim3(DIM / 32, FFN / 32, 1),  tb>>>(sW2, FFN, DIM, 1);
    k_transpose<<<dim3(DIM / 32, DIM / 32, 1),  tb>>>(sWg, DIM, DIM, 2);
    k_transpose<<<dim3(FFN / 32, DIM / 32, NE), tb>>>(dW1, DIM, FFN, 3);
    k_transpose<<<dim3(DIM / 32, FFN / 32, NE), tb>>>(dW2, FFN, DIM, 4);
    k_transpose<<<dim3(DIM / 32, DIM / 32, NE), tb>>>(dWg, DIM, DIM, 5);

    // shared expert (all tokens)
    gemm_k<0, false><<<dim3(FFN / 128, NTOK / 128, 1), 256, SMEM_BYTES>>>(x, sb1, nullptr, DIM, FFN);
    gemm_k<1, false><<<dim3(DIM / 128, NTOK / 128, 1), 256, SMEM_BYTES>>>(x, sb2, nullptr, FFN, DIM);
    gemm_k<2, false><<<dim3(DIM / 128, NTOK / 128, 1), 256, SMEM_BYTES>>>(x, sbg, out,     DIM, DIM);

    // domain experts via packed tile table (gridY = 74 >= max tiles)
    gemm_k<0, true><<<dim3(FFN / 128, 74, 1), 256, SMEM_BYTES>>>(x, db1, nullptr, DIM, FFN);
    gemm_k<1, true><<<dim3(DIM / 128, 74, 1), 256, SMEM_BYTES>>>(x, db2, nullptr, FFN, DIM);
    gemm_k<2, true><<<dim3(DIM / 128, 74, 1), 256, SMEM_BYTES>>>(x, dbg, out,     DIM, DIM);
}

// round 7
// speedup vs baseline: 1.1466x; 1.1466x over previous
#include <cuda_runtime.h>
#include <cuda_bf16.h>
#include <math.h>
#include <stdint.h>

#define NTOK 8192
#define DIM  1024
#define FFN  4096
#define NE   10

typedef __nv_bfloat16 bf16;

// ---------------- scratch (device globals: no allocation allowed) ----------
__device__ bf16  g_Ab [(size_t)NTOK * FFN];   // gelu activations, bf16
__device__ float g_H  [(size_t)NTOK * DIM];   // h (fp32)
__device__ float g_Xg [(size_t)NTOK * DIM];   // gathered x, fp32 (residual/mix)
__device__ bf16  g_Xb [(size_t)NTOK * DIM];   // x bf16 (token order)
__device__ bf16  g_Xgb[(size_t)NTOK * DIM];   // gathered x bf16 (perm order)
__device__ int   g_perm[NTOK];
__device__ int   g_cnt[NE];
__device__ int   g_off[NE];
__device__ int   g_cur[NE];
__device__ int   g_tileTab[80];               // (e<<16)|rowTileIdx
__device__ int   g_ntile;

// transposed bf16 weights: Wt[n*K + k] = bf16(W[k*N + n])
__device__ bf16 g_sW1t[(size_t)FFN * DIM];
__device__ bf16 g_sW2t[(size_t)DIM * FFN];
__device__ bf16 g_sWgt[(size_t)DIM * DIM];
__device__ bf16 g_dW1t[(size_t)NE * FFN * DIM];
__device__ bf16 g_dW2t[(size_t)NE * DIM * FFN];
__device__ bf16 g_dWgt[(size_t)NE * DIM * DIM];

// ---------------- PTX helpers ------------------------------------------------
__device__ __forceinline__ uint32_t smem_u32(const void* p) {
    uint32_t a;
    asm("{ .reg .u64 t; cvta.to.shared.u64 t, %1; cvt.u32.u64 %0, t; }" : "=r"(a) : "l"(p));
    return a;
}
__device__ __forceinline__ void cp16(uint32_t dst, const void* src, int srcbytes) {
    asm volatile("cp.async.cg.shared.global [%0], [%1], 16, %2;"
                 :: "r"(dst), "l"(src), "r"(srcbytes) : "memory");
}
__device__ __forceinline__ void cp_commit() {
    asm volatile("cp.async.commit_group;" ::: "memory");
}
template <int N>
__device__ __forceinline__ void cp_wait() {
    asm volatile("cp.async.wait_group %0;" :: "n"(N) : "memory");
}
__device__ __forceinline__ void ldsm_x4(uint32_t* r, uint32_t addr) {
    asm volatile("ldmatrix.sync.aligned.m8n8.x4.shared.b16 {%0,%1,%2,%3}, [%4];"
                 : "=r"(r[0]), "=r"(r[1]), "=r"(r[2]), "=r"(r[3]) : "r"(addr));
}
__device__ __forceinline__ void ldsm_x2(uint32_t* r, uint32_t addr) {
    asm volatile("ldmatrix.sync.aligned.m8n8.x2.shared.b16 {%0,%1}, [%2];"
                 : "=r"(r[0]), "=r"(r[1]) : "r"(addr));
}
__device__ __forceinline__ void mma_bf16(float* c, const uint32_t* a, const uint32_t* b) {
    asm volatile(
        "mma.sync.aligned.m16n8k16.row.col.f32.bf16.bf16.f32 "
        "{%0,%1,%2,%3},{%4,%5,%6,%7},{%8,%9},{%0,%1,%2,%3};"
        : "+f"(c[0]), "+f"(c[1]), "+f"(c[2]), "+f"(c[3])
        : "r"(a[0]), "r"(a[1]), "r"(a[2]), "r"(a[3]), "r"(b[0]), "r"(b[1]));
}

// ---------------- routing ---------------------------------------------------
__global__ void k_zero() {
    int i = threadIdx.x;
    if (i < NE) { g_cnt[i] = 0; g_cur[i] = 0; }
}
__global__ void k_count(const int* __restrict__ ids) {
    int i = blockIdx.x * blockDim.x + threadIdx.x;
    if (i < NTOK) atomicAdd(&g_cnt[ids[i]], 1);
}
__global__ void k_scan() {
    if (threadIdx.x == 0) {
        int s = 0;
        for (int e = 0; e < NE; e++) { g_off[e] = s; s += g_cnt[e]; }
        int t = 0;
        for (int e = 0; e < NE; e++) {
            int nt = (g_cnt[e] + 127) >> 7;
            for (int q = 0; q < nt; q++) g_tileTab[t++] = (e << 16) | q;
        }
        g_ntile = t;
    }
}
__global__ void k_scatter(const int* __restrict__ ids) {
    int i = blockIdx.x * blockDim.x + threadIdx.x;
    if (i < NTOK) {
        int e = ids[i];
        int p = g_off[e] + atomicAdd(&g_cur[e], 1);
        g_perm[p] = i;
    }
}
__global__ void k_gather(const float* __restrict__ x) {
    int p   = blockIdx.x;
    int src = g_perm[p];
    float4 v = ((const float4*)(x + (size_t)src * DIM))[threadIdx.x];
    ((float4*)(g_Xg + (size_t)p * DIM))[threadIdx.x] = v;
    union { __nv_bfloat162 h; uint32_t u; } a, b;
    a.h = __floats2bfloat162_rn(v.x, v.y);
    b.h = __floats2bfloat162_rn(v.z, v.w);
    ((uint2*)(g_Xgb + (size_t)p * DIM))[threadIdx.x] = make_uint2(a.u, b.u);
}

// ---------------- converts ---------------------------------------------------
__global__ void k_cvt_x(const float* __restrict__ x) {
    int i = blockIdx.x * blockDim.x + threadIdx.x;
    float4 v = ((const float4*)x)[i];
    union { __nv_bfloat162 h; uint32_t u; } a, b;
    a.h = __floats2bfloat162_rn(v.x, v.y);
    b.h = __floats2bfloat162_rn(v.z, v.w);
    ((uint2*)g_Xb)[i] = make_uint2(a.u, b.u);
}
__global__ void k_transpose(const float* __restrict__ W, int K, int N, int which) {
    bf16* Wt = which == 0 ? g_sW1t : which == 1 ? g_sW2t : which == 2 ? g_sWgt
             : which == 3 ? g_dW1t : which == 4 ? g_dW2t : g_dWgt;
    int e = blockIdx.z;
    W  += (size_t)e * K * N;
    Wt += (size_t)e * K * N;
    __shared__ float t[32][33];
    int n0 = blockIdx.x * 32, k0 = blockIdx.y * 32;
#pragma unroll
    for (int i = threadIdx.y; i < 32; i += 8)
        t[i][threadIdx.x] = W[(size_t)(k0 + i) * N + n0 + threadIdx.x];
    __syncthreads();
#pragma unroll
    for (int i = threadIdx.y; i < 32; i += 8)
        Wt[(size_t)(n0 + i) * K + k0 + threadIdx.x] = __float2bfloat16(t[threadIdx.x][i]);
}

// ---------------- bf16 tensor-core GEMM --------------------------------------
// BM=128, BN=128, BK=64, 256 threads (8 warps 2x4), warp tile 64x32.
// 3-stage cp.async pipeline, ONE __syncthreads per 64-wide K-chunk.
#define APAD   72                 // row stride in elems (144B = 16B aligned; bank offset 4r)
#define BUFB   (128 * APAD)       // elems per operand per stage
#define STAGES 3
#define SMEM_BYTES (STAGES * 2 * BUFB * 2)   // 110592 B

template <int MODE, bool DOMAIN>
__global__ void __launch_bounds__(256, 2) gemm_k(
    const float* __restrict__ xf,
    const float* __restrict__ biasBase,
    float*       __restrict__ Fout,
    int K, int Nd)
{
    int e = 0, Mloc = NTOK, rowBase = 0, rowTile;
    if (DOMAIN) {
        int idx = blockIdx.y;
        if (idx >= g_ntile) return;
        int pk  = g_tileTab[idx];
        e       = pk >> 16;
        rowTile = (pk & 0xffff) * 128;
        Mloc    = g_cnt[e];
        rowBase = g_off[e];
    } else {
        rowTile = blockIdx.y * 128;
    }

    const bf16* A;
    if (MODE == 1) A = g_Ab + (size_t)rowBase * K;
    else           A = (DOMAIN ? g_Xgb : g_Xb) + (size_t)rowBase * K;
    const bf16* Wt =
        MODE == 0 ? (DOMAIN ? g_dW1t : g_sW1t)
      : MODE == 1 ? (DOMAIN ? g_dW2t : g_sW2t)
                  : (DOMAIN ? g_dWgt : g_sWgt);
    if (DOMAIN) Wt += (size_t)e * K * Nd;
    const float* bias = biasBase + (DOMAIN ? (size_t)e * Nd : 0);
    const float* Xr   = DOMAIN ? g_Xg : xf;

    extern __shared__ bf16 sm[];
    uint32_t asb = smem_u32(sm);                 // A stages
    uint32_t bsb = asb + STAGES * BUFB * 2;      // B stages

    int tid   = threadIdx.x;
    int lane  = tid & 31;
    int warp  = tid >> 5;
    int warpM = warp >> 2;
    int warpN = warp & 3;

    int colTile = blockIdx.x * 128;

    // staging map (BK=64): 128 rows x 64 elems per operand; 4 cp16/thread/operand
    int srow = tid >> 3;          // 0..31 (+p*32)
    int sseg = (tid & 7) * 8;     // elem offset 0..56

    int aoff = (lane & 15) * APAD + ((lane >> 4) << 3);
    int boff = (lane & 7)  * APAD + (((lane >> 3) & 1) << 3);

    float acc[4][4][4];
#pragma unroll
    for (int mi = 0; mi < 4; mi++)
#pragma unroll
        for (int ni = 0; ni < 4; ni++)
#pragma unroll
            for (int j = 0; j < 4; j++) acc[mi][ni][j] = 0.f;

    const int chunks = K >> 6;

#define ISSUE(chunk, slot)                                                        \
    do {                                                                          \
        int _kk = (chunk) << 6;                                                   \
        uint32_t _aO = asb + (uint32_t)(slot) * BUFB * 2;                         \
        uint32_t _bO = bsb + (uint32_t)(slot) * BUFB * 2;                         \
        _Pragma("unroll")                                                         \
        for (int _p = 0; _p < 4; _p++) {                                          \
            int _row = srow + _p * 32;                                            \
            int _av  = (rowTile + _row) < Mloc ? 16 : 0;                          \
            cp16(_aO + (uint32_t)(_row * APAD + sseg) * 2,                        \
                 A + (size_t)(rowTile + _row) * K + _kk + sseg, _av);             \
            cp16(_bO + (uint32_t)(_row * APAD + sseg) * 2,                        \
                 Wt + (size_t)(colTile + _row) * K + _kk + sseg, 16);             \
        }                                                                         \
        cp_commit();                                                              \
    } while (0)

    ISSUE(0, 0);
    if (chunks > 1) ISSUE(1, 1);

    int sCur = 0;
    for (int i = 0; i < chunks; i++) {
        if (i + 1 < chunks) cp_wait<1>();
        else                cp_wait<0>();
        __syncthreads();

        if (i + 2 < chunks) {
            int slot = sCur + 2; if (slot >= STAGES) slot -= STAGES;
            ISSUE(i + 2, slot);
        }

        uint32_t aBuf = asb + (uint32_t)sCur * BUFB * 2;
        uint32_t bBuf = bsb + (uint32_t)sCur * BUFB * 2;
#pragma unroll
        for (int kb = 0; kb < 64; kb += 16) {
            uint32_t af[4][4], bfr[4][2];
#pragma unroll
            for (int mi = 0; mi < 4; mi++)
                ldsm_x4(af[mi], aBuf + (uint32_t)((warpM * 64 + mi * 16) * APAD + kb + aoff) * 2);
#pragma unroll
            for (int ni = 0; ni < 4; ni++)
                ldsm_x2(bfr[ni], bBuf + (uint32_t)((warpN * 32 + ni * 8) * APAD + kb + boff) * 2);
#pragma unroll
            for (int mi = 0; mi < 4; mi++)
#pragma unroll
                for (int ni = 0; ni < 4; ni++)
                    mma_bf16(acc[mi][ni], af[mi], bfr[ni]);
        }
        if (++sCur == STAGES) sCur = 0;
    }
#undef ISSUE

    // ---------------- epilogue ----------------
    int grp = lane >> 2;
    int t4  = lane & 3;
#pragma unroll
    for (int mi = 0; mi < 4; mi++) {
#pragma unroll
        for (int h = 0; h < 2; h++) {
            int lr = rowTile + warpM * 64 + mi * 16 + grp + h * 8;
            if (lr >= Mloc) continue;
            int grow = rowBase + lr;
#pragma unroll
            for (int ni = 0; ni < 4; ni++) {
                int col = colTile + warpN * 32 + ni * 8 + t4 * 2;
                float v0 = acc[mi][ni][h * 2 + 0];
                float v1 = acc[mi][ni][h * 2 + 1];

                if (MODE == 0) {
                    float a0 = v0 + bias[col];
                    float a1 = v1 + bias[col + 1];
                    a0 = 0.5f * a0 * (1.0f + erff(a0 * 0.70710678118654752f));
                    a1 = 0.5f * a1 * (1.0f + erff(a1 * 0.70710678118654752f));
                    union { __nv_bfloat162 h2; uint32_t u; } cv;
                    cv.h2 = __floats2bfloat162_rn(a0, a1);
                    *(uint32_t*)(g_Ab + (size_t)grow * Nd + col) = cv.u;
                } else if (MODE == 1) {
                    float*       dst = g_H + (size_t)grow * Nd + col;
                    const float* r   = Xr  + (size_t)grow * Nd + col;
                    dst[0] = v0 + bias[col]     + r[0];
                    dst[1] = v1 + bias[col + 1] + r[1];
                } else {
                    const float* hp = g_H + (size_t)grow * Nd + col;
                    const float* xp = Xr  + (size_t)grow * Nd + col;
                    int orow = DOMAIN ? g_perm[grow] : grow;
                    float* dst = Fout + (size_t)orow * Nd + col;
                    float g0 = 1.0f / (1.0f + expf(-(v0 + bias[col])));
                    float g1 = 1.0f / (1.0f + expf(-(v1 + bias[col + 1])));
                    float o0 = g0 * hp[0] + (1.0f - g0) * xp[0];
                    float o1 = g1 * hp[1] + (1.0f - g1) * xp[1];
                    if (DOMAIN) { dst[0] += o0; dst[1] += o1; }
                    else        { dst[0]  = o0; dst[1]  = o1; }
                }
            }
        }
    }
}

// ---------------- launch -----------------------------------------------------
extern "C" void kernel_launch(void* const* d_in, const int* in_sizes, int n_in,
                              void* d_out, int out_size)
{
    const float* x   = (const float*)d_in[0];
    const int*   ids = (const int*)  d_in[1];
    const float* sW1 = (const float*)d_in[2];
    const float* sb1 = (const float*)d_in[3];
    const float* sW2 = (const float*)d_in[4];
    const float* sb2 = (const float*)d_in[5];
    const float* sWg = (const float*)d_in[6];
    const float* sbg = (const float*)d_in[7];
    const float* dW1 = (const float*)d_in[8];
    const float* db1 = (const float*)d_in[9];
    const float* dW2 = (const float*)d_in[10];
    const float* db2 = (const float*)d_in[11];
    const float* dWg = (const float*)d_in[12];
    const float* dbg = (const float*)d_in[13];
    float* out = (float*)d_out;

    cudaFuncSetAttribute(gemm_k<0, false>, cudaFuncAttributeMaxDynamicSharedMemorySize, SMEM_BYTES);
    cudaFuncSetAttribute(gemm_k<1, false>, cudaFuncAttributeMaxDynamicSharedMemorySize, SMEM_BYTES);
    cudaFuncSetAttribute(gemm_k<2, false>, cudaFuncAttributeMaxDynamicSharedMemorySize, SMEM_BYTES);
    cudaFuncSetAttribute(gemm_k<0, true>,  cudaFuncAttributeMaxDynamicSharedMemorySize, SMEM_BYTES);
    cudaFuncSetAttribute(gemm_k<1, true>,  cudaFuncAttributeMaxDynamicSharedMemorySize, SMEM_BYTES);
    cudaFuncSetAttribute(gemm_k<2, true>,  cudaFuncAttributeMaxDynamicSharedMemorySize, SMEM_BYTES);

    // routing + converts
    k_zero   <<<1, 32>>>();
    k_count  <<<NTOK / 256, 256>>>(ids);
    k_scan   <<<1, 32>>>();
    k_scatter<<<NTOK / 256, 256>>>(ids);
    k_gather <<<NTOK, 256>>>(x);
    k_cvt_x  <<<NTOK * DIM / 4 / 256, 256>>>(x);

    dim3 tb(32, 8);
    k_transpose<<<dim3(FFN / 32, DIM / 32, 1),  tb>>>(sW1, DIM, FFN, 0);
    k_transpose<<<dim3(DIM / 32, FFN / 32, 1),  tb>>>(sW2, FFN, DIM, 1);
    k_transpose<<<dim3(DIM / 32, DIM / 32, 1),  tb>>>(sWg, DIM, DIM, 2);
    k_transpose<<<dim3(FFN / 32, DIM / 32, NE), tb>>>(dW1, DIM, FFN, 3);
    k_transpose<<<dim3(DIM / 32, FFN / 32, NE), tb>>>(dW2, FFN, DIM, 4);
    k_transpose<<<dim3(DIM / 32, DIM / 32, NE), tb>>>(dWg, DIM, DIM, 5);

    // shared expert (all tokens)
    gemm_k<0, false><<<dim3(FFN / 128, NTOK / 128, 1), 256, SMEM_BYTES>>>(x, sb1, nullptr, DIM, FFN);
    gemm_k<1, false><<<dim3(DIM / 128, NTOK / 128, 1), 256, SMEM_BYTES>>>(x, sb2, nullptr, FFN, DIM);
    gemm_k<2, false><<<dim3(DIM / 128, NTOK / 128, 1), 256, SMEM_BYTES>>>(x, sbg, out,     DIM, DIM);

    // domain experts via packed tile table (gridY = 74 >= max tiles)
    gemm_k<0, true><<<dim3(FFN / 128, 74, 1), 256, SMEM_BYTES>>>(x, db1, nullptr, DIM, FFN);
    gemm_k<1, true><<<dim3(DIM / 128, 74, 1), 256, SMEM_BYTES>>>(x, db2, nullptr, FFN, DIM);
    gemm_k<2, true><<<dim3(DIM / 128, 74, 1), 256, SMEM_BYTES>>>(x, dbg, out,     DIM, DIM);
}

// round 8
// speedup vs baseline: 1.1512x; 1.0040x over previous
#include <cuda_runtime.h>
#include <cuda_bf16.h>
#include <math.h>
#include <stdint.h>

#define NTOK 8192
#define DIM  1024
#define FFN  4096
#define NE   10

typedef __nv_bfloat16 bf16;

// ---------------- scratch (device globals: no allocation allowed) ----------
__device__ bf16    g_Ab [(size_t)NTOK * FFN];   // shared gelu acts (token rows)
__device__ bf16    g_Ad [(size_t)NTOK * FFN];   // domain gelu acts (perm rows)
__device__ float   g_H  [(size_t)NTOK * DIM];   // shared h
__device__ float   g_Hd [(size_t)NTOK * DIM];   // domain h (perm rows)
__device__ float   g_Xg [(size_t)NTOK * DIM];   // gathered x fp32 (perm rows)
__device__ bf16    g_Xb [(size_t)NTOK * DIM];   // x bf16 (token rows)
__device__ bf16    g_Xgb[(size_t)NTOK * DIM];   // gathered x bf16 (perm rows)
__device__ uint8_t g_X8 [(size_t)NTOK * DIM];   // x fp8 (token rows)
__device__ uint8_t g_Xg8[(size_t)NTOK * DIM];   // gathered x fp8 (perm rows)
__device__ int     g_perm[NTOK];
__device__ int     g_cnt[NE];
__device__ int     g_off[NE];
__device__ int     g_cur[NE];
__device__ int     g_tileTab[80];
__device__ int     g_ntile;

// transposed weights: Wt[n*K + k] = W[k*N + n]; W1 in fp8, rest bf16
__device__ uint8_t g_sW18[(size_t)FFN * DIM];
__device__ uint8_t g_dW18[(size_t)NE * FFN * DIM];
__device__ bf16    g_sW2t[(size_t)DIM * FFN];
__device__ bf16    g_sWgt[(size_t)DIM * DIM];
__device__ bf16    g_dW2t[(size_t)NE * DIM * FFN];
__device__ bf16    g_dWgt[(size_t)NE * DIM * DIM];

// ---------------- PTX helpers ------------------------------------------------
__device__ __forceinline__ uint32_t smem_u32(const void* p) {
    uint32_t a;
    asm("{ .reg .u64 t; cvta.to.shared.u64 t, %1; cvt.u32.u64 %0, t; }" : "=r"(a) : "l"(p));
    return a;
}
__device__ __forceinline__ void cp16(uint32_t dst, const void* src, int srcbytes) {
    asm volatile("cp.async.cg.shared.global [%0], [%1], 16, %2;"
                 :: "r"(dst), "l"(src), "r"(srcbytes) : "memory");
}
__device__ __forceinline__ void cp_commit() {
    asm volatile("cp.async.commit_group;" ::: "memory");
}
template <int N>
__device__ __forceinline__ void cp_wait() {
    asm volatile("cp.async.wait_group %0;" :: "n"(N) : "memory");
}
__device__ __forceinline__ void ldsm_x4(uint32_t* r, uint32_t addr) {
    asm volatile("ldmatrix.sync.aligned.m8n8.x4.shared.b16 {%0,%1,%2,%3}, [%4];"
                 : "=r"(r[0]), "=r"(r[1]), "=r"(r[2]), "=r"(r[3]) : "r"(addr));
}
__device__ __forceinline__ void ldsm_x2(uint32_t* r, uint32_t addr) {
    asm volatile("ldmatrix.sync.aligned.m8n8.x2.shared.b16 {%0,%1}, [%2];"
                 : "=r"(r[0]), "=r"(r[1]) : "r"(addr));
}
__device__ __forceinline__ void mma_bf16(float* c, const uint32_t* a, const uint32_t* b) {
    asm volatile(
        "mma.sync.aligned.m16n8k16.row.col.f32.bf16.bf16.f32 "
        "{%0,%1,%2,%3},{%4,%5,%6,%7},{%8,%9},{%0,%1,%2,%3};"
        : "+f"(c[0]), "+f"(c[1]), "+f"(c[2]), "+f"(c[3])
        : "r"(a[0]), "r"(a[1]), "r"(a[2]), "r"(a[3]), "r"(b[0]), "r"(b[1]));
}
__device__ __forceinline__ void mma_fp8(float* c, const uint32_t* a, const uint32_t* b) {
    asm volatile(
        "mma.sync.aligned.m16n8k32.row.col.f32.e4m3.e4m3.f32 "
        "{%0,%1,%2,%3},{%4,%5,%6,%7},{%8,%9},{%0,%1,%2,%3};"
        : "+f"(c[0]), "+f"(c[1]), "+f"(c[2]), "+f"(c[3])
        : "r"(a[0]), "r"(a[1]), "r"(a[2]), "r"(a[3]), "r"(b[0]), "r"(b[1]));
}
__device__ __forceinline__ uint16_t f2e4m3x2(float hi, float lo) {
    uint16_t r;
    asm("cvt.rn.satfinite.e4m3x2.f32 %0, %1, %2;" : "=h"(r) : "f"(hi), "f"(lo));
    return r;
}

// ---------------- routing ---------------------------------------------------
__global__ void k_zero() {
    int i = threadIdx.x;
    if (i < NE) { g_cnt[i] = 0; g_cur[i] = 0; }
}
__global__ void k_count(const int* __restrict__ ids) {
    int i = blockIdx.x * blockDim.x + threadIdx.x;
    if (i < NTOK) atomicAdd(&g_cnt[ids[i]], 1);
}
__global__ void k_scan() {
    if (threadIdx.x == 0) {
        int s = 0;
        for (int e = 0; e < NE; e++) { g_off[e] = s; s += g_cnt[e]; }
        int t = 0;
        for (int e = 0; e < NE; e++) {
            int nt = (g_cnt[e] + 127) >> 7;
            for (int q = 0; q < nt; q++) g_tileTab[t++] = (e << 16) | q;
        }
        g_ntile = t;
    }
}
__global__ void k_scatter(const int* __restrict__ ids) {
    int i = blockIdx.x * blockDim.x + threadIdx.x;
    if (i < NTOK) {
        int e = ids[i];
        int p = g_off[e] + atomicAdd(&g_cur[e], 1);
        g_perm[p] = i;
    }
}
__global__ void k_gather(const float* __restrict__ x) {
    int p   = blockIdx.x;
    int src = g_perm[p];
    float4 v = ((const float4*)(x + (size_t)src * DIM))[threadIdx.x];
    ((float4*)(g_Xg + (size_t)p * DIM))[threadIdx.x] = v;
    union { __nv_bfloat162 h; uint32_t u; } a, b;
    a.h = __floats2bfloat162_rn(v.x, v.y);
    b.h = __floats2bfloat162_rn(v.z, v.w);
    ((uint2*)(g_Xgb + (size_t)p * DIM))[threadIdx.x] = make_uint2(a.u, b.u);
    uint32_t q = ((uint32_t)f2e4m3x2(v.w, v.z) << 16) | f2e4m3x2(v.y, v.x);
    ((uint32_t*)(g_Xg8 + (size_t)p * DIM))[threadIdx.x] = q;
}

// ---------------- converts ---------------------------------------------------
__global__ void k_cvt_x(const float* __restrict__ x) {
    int i = blockIdx.x * blockDim.x + threadIdx.x;
    float4 v = ((const float4*)x)[i];
    union { __nv_bfloat162 h; uint32_t u; } a, b;
    a.h = __floats2bfloat162_rn(v.x, v.y);
    b.h = __floats2bfloat162_rn(v.z, v.w);
    ((uint2*)g_Xb)[i] = make_uint2(a.u, b.u);
    uint32_t q = ((uint32_t)f2e4m3x2(v.w, v.z) << 16) | f2e4m3x2(v.y, v.x);
    ((uint32_t*)g_X8)[i] = q;
}
// bf16 transpose (W2, Wg)
__global__ void k_transpose(const float* __restrict__ W, int K, int N, int which) {
    bf16* Wt = which == 1 ? g_sW2t : which == 2 ? g_sWgt
             : which == 4 ? g_dW2t : g_dWgt;
    int e = blockIdx.z;
    W  += (size_t)e * K * N;
    Wt += (size_t)e * K * N;
    __shared__ float t[32][33];
    int n0 = blockIdx.x * 32, k0 = blockIdx.y * 32;
#pragma unroll
    for (int i = threadIdx.y; i < 32; i += 8)
        t[i][threadIdx.x] = W[(size_t)(k0 + i) * N + n0 + threadIdx.x];
    __syncthreads();
#pragma unroll
    for (int i = threadIdx.y; i < 32; i += 8)
        Wt[(size_t)(n0 + i) * K + k0 + threadIdx.x] = __float2bfloat16(t[threadIdx.x][i]);
}
// fp8 transpose (W1): which8 0 -> sW18, 1 -> dW18
__global__ void k_transpose8(const float* __restrict__ W, int K, int N, int which8) {
    uint8_t* Wt = which8 == 0 ? g_sW18 : g_dW18;
    int e = blockIdx.z;
    W  += (size_t)e * K * N;
    Wt += (size_t)e * K * N;
    __shared__ float t[32][33];
    int n0 = blockIdx.x * 32, k0 = blockIdx.y * 32;
#pragma unroll
    for (int i = threadIdx.y; i < 32; i += 8)
        t[i][threadIdx.x] = W[(size_t)(k0 + i) * N + n0 + threadIdx.x];
    __syncthreads();
    int tid = threadIdx.y * 32 + threadIdx.x;
    int row = tid >> 3;          // n index 0..31
    int kq  = (tid & 7) * 4;     // k offset 0..28
    float v0 = t[kq + 0][row], v1 = t[kq + 1][row];
    float v2 = t[kq + 2][row], v3 = t[kq + 3][row];
    uint32_t u = ((uint32_t)f2e4m3x2(v3, v2) << 16) | f2e4m3x2(v1, v0);
    *(uint32_t*)(Wt + (size_t)(n0 + row) * K + k0 + kq) = u;
}

// ---------------- tiling constants -------------------------------------------
#define ROWB   144                 // staged row stride bytes (128B payload + 16 pad)
#define BUFBY  (128 * ROWB)        // bytes per operand per stage
#define STAGES 3
#define SMEM_BYTES (STAGES * 2 * BUFBY)   // 110592 B

// resolve (shared|domain) tile coords; returns false if CTA should exit
__device__ __forceinline__ bool tile_coords(int by, int domSel, bool& dom, int& e,
                                            int& Mloc, int& rowBase, int& rowTile) {
    if (domSel < 0) { dom = by >= 64; if (dom) by -= 64; }
    else            dom = domSel != 0;
    if (!dom) {
        e = 0; Mloc = NTOK; rowBase = 0; rowTile = by * 128;
    } else {
        if (by >= g_ntile) return false;
        int pk  = g_tileTab[by];
        e       = pk >> 16;
        rowTile = (pk & 0xffff) * 128;
        Mloc    = g_cnt[e];
        rowBase = g_off[e];
    }
    return true;
}

// ---------------- GEMM1: fp8, merged shared+domain ---------------------------
// C = gelu(A@W1 + b1) -> bf16 (shared: g_Ab token rows; domain: g_Ad perm rows)
__global__ void __launch_bounds__(256, 2) gemm_fp8(
    const float* __restrict__ sb1, const float* __restrict__ db1)
{
    bool dom; int e, Mloc, rowBase, rowTile;
    if (!tile_coords(blockIdx.y, -1, dom, e, Mloc, rowBase, rowTile)) return;

    const int K = DIM, Nd = FFN;
    const uint8_t* A8 = dom ? g_Xg8 + (size_t)rowBase * K : g_X8;
    const uint8_t* W8 = dom ? g_dW18 + (size_t)e * K * Nd : g_sW18;
    const float* bias = dom ? db1 + (size_t)e * Nd : sb1;
    bf16* dstA        = dom ? g_Ad : g_Ab;

    extern __shared__ uint8_t sm[];
    uint32_t asb = smem_u32(sm);
    uint32_t bsb = asb + STAGES * BUFBY;

    int tid   = threadIdx.x;
    int lane  = tid & 31;
    int warp  = tid >> 5;
    int warpM = warp >> 2;
    int warpN = warp & 3;
    int colTile = blockIdx.x * 128;

    int srow = tid >> 3;             // 0..31 (+p*32)
    int sseg = (tid & 7) * 16;       // byte offset in 128B row

    int aoffB = (lane & 15) * ROWB + ((lane >> 4) << 4);
    int boffB = (lane & 7)  * ROWB + (((lane >> 3) & 1) << 4);

    float acc[4][4][4];
#pragma unroll
    for (int mi = 0; mi < 4; mi++)
#pragma unroll
        for (int ni = 0; ni < 4; ni++)
#pragma unroll
            for (int j = 0; j < 4; j++) acc[mi][ni][j] = 0.f;

    const int chunks = K >> 7;       // 128 fp8 per chunk -> 8

#define ISSUE8(chunk, slot)                                                       \
    do {                                                                          \
        int _kk = (chunk) << 7;                                                   \
        uint32_t _aO = asb + (uint32_t)(slot) * BUFBY;                            \
        uint32_t _bO = bsb + (uint32_t)(slot) * BUFBY;                            \
        _Pragma("unroll")                                                         \
        for (int _p = 0; _p < 4; _p++) {                                          \
            int _row = srow + _p * 32;                                            \
            int _av  = (rowTile + _row) < Mloc ? 16 : 0;                          \
            cp16(_aO + (uint32_t)(_row * ROWB + sseg),                            \
                 A8 + (size_t)(rowTile + _row) * K + _kk + sseg, _av);            \
            cp16(_bO + (uint32_t)(_row * ROWB + sseg),                            \
                 W8 + (size_t)(colTile + _row) * K + _kk + sseg, 16);             \
        }                                                                         \
        cp_commit();                                                              \
    } while (0)

    ISSUE8(0, 0);
    ISSUE8(1, 1);

    int sCur = 0;
    for (int i = 0; i < chunks; i++) {
        if (i + 1 < chunks) cp_wait<1>();
        else                cp_wait<0>();
        __syncthreads();
        if (i + 2 < chunks) {
            int slot = sCur + 2; if (slot >= STAGES) slot -= STAGES;
            ISSUE8(i + 2, slot);
        }
        uint32_t aBuf = asb + (uint32_t)sCur * BUFBY;
        uint32_t bBuf = bsb + (uint32_t)sCur * BUFBY;
#pragma unroll
        for (int ks = 0; ks < 4; ks++) {          // 4 x k32 per 128-fp8 chunk
            uint32_t af[4][4], bfr[4][2];
#pragma unroll
            for (int mi = 0; mi < 4; mi++)
                ldsm_x4(af[mi], aBuf + (uint32_t)((warpM * 64 + mi * 16) * ROWB + ks * 32 + aoffB));
#pragma unroll
            for (int ni = 0; ni < 4; ni++)
                ldsm_x2(bfr[ni], bBuf + (uint32_t)((warpN * 32 + ni * 8) * ROWB + ks * 32 + boffB));
#pragma unroll
            for (int mi = 0; mi < 4; mi++)
#pragma unroll
                for (int ni = 0; ni < 4; ni++)
                    mma_fp8(acc[mi][ni], af[mi], bfr[ni]);
        }
        if (++sCur == STAGES) sCur = 0;
    }
#undef ISSUE8

    int grp = lane >> 2, t4 = lane & 3;
#pragma unroll
    for (int mi = 0; mi < 4; mi++)
#pragma unroll
        for (int h = 0; h < 2; h++) {
            int lr = rowTile + warpM * 64 + mi * 16 + grp + h * 8;
            if (lr >= Mloc) continue;
            int grow = dom ? rowBase + lr : lr;
#pragma unroll
            for (int ni = 0; ni < 4; ni++) {
                int col = colTile + warpN * 32 + ni * 8 + t4 * 2;
                float a0 = acc[mi][ni][h * 2 + 0] + bias[col];
                float a1 = acc[mi][ni][h * 2 + 1] + bias[col + 1];
                a0 = 0.5f * a0 * (1.0f + erff(a0 * 0.70710678118654752f));
                a1 = 0.5f * a1 * (1.0f + erff(a1 * 0.70710678118654752f));
                union { __nv_bfloat162 h2; uint32_t u; } cv;
                cv.h2 = __floats2bfloat162_rn(a0, a1);
                *(uint32_t*)(dstA + (size_t)grow * Nd + col) = cv.u;
            }
        }
}

// ---------------- GEMM2/3: bf16 ----------------------------------------------
// MODE 1: h = A@W2 + b2 + x  (dst g_H / g_Hd)      [merged launch, domSel=-1]
// MODE 2: g = sigmoid(x@Wg + bg); out = g*h+(1-g)*x [shared then domain launch]
template <int MODE>
__global__ void __launch_bounds__(256, 2) gemm_bf(
    const float* __restrict__ xf,
    const float* __restrict__ sbias, const float* __restrict__ dbias,
    float* __restrict__ Fout, int K, int Nd, int domSel)
{
    bool dom; int e, Mloc, rowBase, rowTile;
    if (!tile_coords(blockIdx.y, domSel, dom, e, Mloc, rowBase, rowTile)) return;

    const bf16* A;
    if (MODE == 1) A = (dom ? g_Ad : g_Ab) + (dom ? (size_t)rowBase * K : 0);
    else           A = dom ? g_Xgb + (size_t)rowBase * K : g_Xb;
    const bf16* Wt = MODE == 1 ? (dom ? g_dW2t + (size_t)e * K * Nd : g_sW2t)
                               : (dom ? g_dWgt + (size_t)e * K * Nd : g_sWgt);
    const float* bias = dom ? dbias + (size_t)e * Nd : sbias;
    const float* Xr   = dom ? g_Xg : xf;
    const float* Hs   = dom ? g_Hd : g_H;

    extern __shared__ uint8_t sm[];
    uint32_t asb = smem_u32(sm);
    uint32_t bsb = asb + STAGES * BUFBY;

    int tid   = threadIdx.x;
    int lane  = tid & 31;
    int warp  = tid >> 5;
    int warpM = warp >> 2;
    int warpN = warp & 3;
    int colTile = blockIdx.x * 128;

    int srow = tid >> 3;             // 0..31 (+p*32)
    int sseg = (tid & 7) * 8;        // elem offset (bf16) 0..56

    int aoffB = (lane & 15) * ROWB + ((lane >> 4) << 4);
    int boffB = (lane & 7)  * ROWB + (((lane >> 3) & 1) << 4);

    float acc[4][4][4];
#pragma unroll
    for (int mi = 0; mi < 4; mi++)
#pragma unroll
        for (int ni = 0; ni < 4; ni++)
#pragma unroll
            for (int j = 0; j < 4; j++) acc[mi][ni][j] = 0.f;

    const int chunks = K >> 6;       // 64 bf16 per chunk

#define ISSUEB(chunk, slot)                                                       \
    do {                                                                          \
        int _kk = (chunk) << 6;                                                   \
        uint32_t _aO = asb + (uint32_t)(slot) * BUFBY;                            \
        uint32_t _bO = bsb + (uint32_t)(slot) * BUFBY;                            \
        _Pragma("unroll")                                                         \
        for (int _p = 0; _p < 4; _p++) {                                          \
            int _row = srow + _p * 32;                                            \
            int _av  = (rowTile + _row) < Mloc ? 16 : 0;                          \
            cp16(_aO + (uint32_t)(_row * ROWB + sseg * 2),                        \
                 A + (size_t)(rowTile + _row) * K + _kk + sseg, _av);             \
            cp16(_bO + (uint32_t)(_row * ROWB + sseg * 2),                        \
                 Wt + (size_t)(colTile + _row) * K + _kk + sseg, 16);             \
        }                                                                         \
        cp_commit();                                                              \
    } while (0)

    ISSUEB(0, 0);
    ISSUEB(1, 1);

    int sCur = 0;
    for (int i = 0; i < chunks; i++) {
        if (i + 1 < chunks) cp_wait<1>();
        else                cp_wait<0>();
        __syncthreads();
        if (i + 2 < chunks) {
            int slot = sCur + 2; if (slot >= STAGES) slot -= STAGES;
            ISSUEB(i + 2, slot);
        }
        uint32_t aBuf = asb + (uint32_t)sCur * BUFBY;
        uint32_t bBuf = bsb + (uint32_t)sCur * BUFBY;
#pragma unroll
        for (int kb = 0; kb < 64; kb += 16) {
            uint32_t af[4][4], bfr[4][2];
#pragma unroll
            for (int mi = 0; mi < 4; mi++)
                ldsm_x4(af[mi], aBuf + (uint32_t)((warpM * 64 + mi * 16) * ROWB + kb * 2 + aoffB));
#pragma unroll
            for (int ni = 0; ni < 4; ni++)
                ldsm_x2(bfr[ni], bBuf + (uint32_t)((warpN * 32 + ni * 8) * ROWB + kb * 2 + boffB));
#pragma unroll
            for (int mi = 0; mi < 4; mi++)
#pragma unroll
                for (int ni = 0; ni < 4; ni++)
                    mma_bf16(acc[mi][ni], af[mi], bfr[ni]);
        }
        if (++sCur == STAGES) sCur = 0;
    }
#undef ISSUEB

    int grp = lane >> 2, t4 = lane & 3;
#pragma unroll
    for (int mi = 0; mi < 4; mi++)
#pragma unroll
        for (int h = 0; h < 2; h++) {
            int lr = rowTile + warpM * 64 + mi * 16 + grp + h * 8;
            if (lr >= Mloc) continue;
            int grow = dom ? rowBase + lr : lr;
#pragma unroll
            for (int ni = 0; ni < 4; ni++) {
                int col = colTile + warpN * 32 + ni * 8 + t4 * 2;
                float v0 = acc[mi][ni][h * 2 + 0];
                float v1 = acc[mi][ni][h * 2 + 1];
                if (MODE == 1) {
                    float*       dst = (dom ? g_Hd : g_H) + (size_t)grow * Nd + col;
                    const float* r   = Xr + (size_t)grow * Nd + col;
                    dst[0] = v0 + bias[col]     + r[0];
                    dst[1] = v1 + bias[col + 1] + r[1];
                } else {
                    const float* hp = Hs + (size_t)grow * Nd + col;
                    const float* xp = Xr + (size_t)grow * Nd + col;
                    int orow = dom ? g_perm[grow] : grow;
                    float* dst = Fout + (size_t)orow * Nd + col;
                    float g0 = 1.0f / (1.0f + expf(-(v0 + bias[col])));
                    float g1 = 1.0f / (1.0f + expf(-(v1 + bias[col + 1])));
                    float o0 = g0 * hp[0] + (1.0f - g0) * xp[0];
                    float o1 = g1 * hp[1] + (1.0f - g1) * xp[1];
                    if (dom) { dst[0] += o0; dst[1] += o1; }
                    else     { dst[0]  = o0; dst[1]  = o1; }
                }
            }
        }
}

// ---------------- launch -----------------------------------------------------
extern "C" void kernel_launch(void* const* d_in, const int* in_sizes, int n_in,
                              void* d_out, int out_size)
{
    const float* x   = (const float*)d_in[0];
    const int*   ids = (const int*)  d_in[1];
    const float* sW1 = (const float*)d_in[2];
    const float* sb1 = (const float*)d_in[3];
    const float* sW2 = (const float*)d_in[4];
    const float* sb2 = (const float*)d_in[5];
    const float* sWg = (const float*)d_in[6];
    const float* sbg = (const float*)d_in[7];
    const float* dW1 = (const float*)d_in[8];
    const float* db1 = (const float*)d_in[9];
    const float* dW2 = (const float*)d_in[10];
    const float* db2 = (const float*)d_in[11];
    const float* dWg = (const float*)d_in[12];
    const float* dbg = (const float*)d_in[13];
    float* out = (float*)d_out;

    cudaFuncSetAttribute(gemm_fp8,   cudaFuncAttributeMaxDynamicSharedMemorySize, SMEM_BYTES);
    cudaFuncSetAttribute(gemm_bf<1>, cudaFuncAttributeMaxDynamicSharedMemorySize, SMEM_BYTES);
    cudaFuncSetAttribute(gemm_bf<2>, cudaFuncAttributeMaxDynamicSharedMemorySize, SMEM_BYTES);

    // routing + converts
    k_zero   <<<1, 32>>>();
    k_count  <<<NTOK / 256, 256>>>(ids);
    k_scan   <<<1, 32>>>();
    k_scatter<<<NTOK / 256, 256>>>(ids);
    k_gather <<<NTOK, 256>>>(x);
    k_cvt_x  <<<NTOK * DIM / 4 / 256, 256>>>(x);

    dim3 tb(32, 8);
    k_transpose8<<<dim3(FFN / 32, DIM / 32, 1),  tb>>>(sW1, DIM, FFN, 0);
    k_transpose8<<<dim3(FFN / 32, DIM / 32, NE), tb>>>(dW1, DIM, FFN, 1);
    k_transpose <<<dim3(DIM / 32, FFN / 32, 1),  tb>>>(sW2, FFN, DIM, 1);
    k_transpose <<<dim3(DIM / 32, DIM / 32, 1),  tb>>>(sWg, DIM, DIM, 2);
    k_transpose <<<dim3(DIM / 32, FFN / 32, NE), tb>>>(dW2, FFN, DIM, 4);
    k_transpose <<<dim3(DIM / 32, DIM / 32, NE), tb>>>(dWg, DIM, DIM, 5);

    // GEMM1 (fp8, merged shared+domain): gridY = 64 shared + 74 domain slots
    gemm_fp8<<<dim3(FFN / 128, 138), 256, SMEM_BYTES>>>(sb1, db1);
    // GEMM2 (bf16, merged)
    gemm_bf<1><<<dim3(DIM / 128, 138), 256, SMEM_BYTES>>>(x, sb2, db2, nullptr, FFN, DIM, -1);
    // GEMM3 gate+mix: shared store first, then domain accumulate (ordering!)
    gemm_bf<2><<<dim3(DIM / 128, 64), 256, SMEM_BYTES>>>(x, sbg, dbg, out, DIM, DIM, 0);
    gemm_bf<2><<<dim3(DIM / 128, 74), 256, SMEM_BYTES>>>(x, sbg, dbg, out, DIM, DIM, 1);
}